// round 5
// baseline (speedup 1.0000x reference)
#include <cuda_runtime.h>
#include <mma.h>
#include <math.h>
#include <stdint.h>

using namespace nvcuda;

#define NNODES 65536
#define NGRAPH 256
#define NPG    256
#define CIN    256
#define KSEL   16
#define ONPG   128
#define H3     64

// scratch (device globals; no allocations allowed)
__device__ float g_h1h[(size_t)NNODES * 256];
__device__ float g_h1l[(size_t)NNODES * 256];
__device__ float g_h2[(size_t)NNODES * 128];
__device__ float g_score[NNODES];
__device__ float g_w1th[256 * 256], g_w1tl[256 * 256];   // W1^T split: [N][K]
__device__ float g_w2th[128 * 256], g_w2tl[128 * 256];   // W2^T split: [N][K]

__device__ __forceinline__ float tf32r(float a) {
    uint32_t u;
    asm("cvt.rna.tf32.f32 %0, %1;" : "=r"(u) : "f"(a));
    return __uint_as_float(u);
}
__device__ __forceinline__ float lrelu(float z) { return z > 0.0f ? z : 0.1f * z; }
__device__ __forceinline__ uint32_t smem_u32(const void* p) {
    uint32_t a;
    asm("{ .reg .u64 t; cvta.to.shared.u64 t, %1; cvt.u32.u64 %0, t; }" : "=r"(a) : "l"(p));
    return a;
}
__device__ __forceinline__ void cp16(uint32_t dst, const void* src) {
    asm volatile("cp.async.cg.shared.global [%0], [%1], 16;" :: "r"(dst), "l"(src));
}
#define CP_COMMIT() asm volatile("cp.async.commit_group;" ::: "memory")
#define CP_WAIT0()  asm volatile("cp.async.wait_group 0;" ::: "memory")

// ============ tf32 3-split GEMM, cp.async pipelined ============
// C = lrelu(A @ Bt^T + bias). A [M,K] row-major (raw fp32 with +pe, or pre-split
// hi/lo pair). Bt pre-split [N][K]. CTA tile 128x128, KC=16, 8 warps (2m x 4n),
// warp tile 64x32 of wmma m16n16k8 tf32 tiles, 3 split terms (hh, lh, hl).
template<bool PRESPLIT_A, bool SPLIT_OUT>
__global__ void __launch_bounds__(256)
tf32cp_gemm(const float* __restrict__ Araw, const float* __restrict__ pe,
            const float* __restrict__ AhG, const float* __restrict__ AlG,
            const float* __restrict__ BhG, const float* __restrict__ BlG,
            const float* __restrict__ bias,
            float* __restrict__ outH, float* __restrict__ outL,
            const int K, const int OutN)
{
    constexpr int KC = 16, PITCH = 20;          // floats
    constexpr int ARRF = 128 * PITCH;           // 2560 floats = 10240 B
    constexpr int BUFF = 4 * ARRF;              // 10240 floats = 40960 B
    extern __shared__ float smf[];
    const uint32_t sbase = smem_u32(smf);

    const int tid = threadIdx.x;
    const int wid = tid >> 5;
    const int wm = wid >> 2;        // 0..1
    const int wn = wid & 3;         // 0..3
    const int row0 = blockIdx.x * 128;
    const int col0 = blockIdx.y * 128;
    const int C = K / KC;

    // cp.async issue: B split always; A split too when PRESPLIT_A
    auto issue = [&](int kt, int b) {
        const uint32_t dbase = sbase + (uint32_t)b * 40960u;
        const int q = tid & 3;
#pragma unroll
        for (int h = 0; h < 2; h++) {
            const int rr = (tid >> 2) + h * 64;
            const uint32_t so = (uint32_t)(rr * 80 + q * 16);
            const size_t gb = (size_t)(col0 + rr) * K + kt + q * 4;
            cp16(dbase + 2u * 10240u + so, BhG + gb);
            cp16(dbase + 3u * 10240u + so, BlG + gb);
            if (PRESPLIT_A) {
                const size_t ga = (size_t)(row0 + rr) * K + kt + q * 4;
                cp16(dbase + so, AhG + ga);
                cp16(dbase + 10240u + so, AlG + ga);
            }
        }
    };

    float4 a4[2], p4[2];
    auto fetchA = [&](int kt) {
#pragma unroll
        for (int i = 0; i < 2; i++) {
            int v = tid + i * 256, r = v >> 2, q = v & 3;
            a4[i] = *reinterpret_cast<const float4*>(&Araw[(size_t)(row0 + r) * K + kt + q * 4]);
            p4[i] = *reinterpret_cast<const float4*>(&pe[(size_t)((row0 + r) & (NPG - 1)) * CIN + kt + q * 4]);
        }
    };
    auto storeA = [&](int b) {
        float* Ah = smf + b * BUFF;
        float* Al = Ah + ARRF;
#pragma unroll
        for (int i = 0; i < 2; i++) {
            int v = tid + i * 256, r = v >> 2, q = v & 3;
            float va[4] = {a4[i].x + p4[i].x, a4[i].y + p4[i].y,
                           a4[i].z + p4[i].z, a4[i].w + p4[i].w};
            float hh[4], ll[4];
#pragma unroll
            for (int j = 0; j < 4; j++) { hh[j] = tf32r(va[j]); ll[j] = tf32r(va[j] - hh[j]); }
            *reinterpret_cast<float4*>(&Ah[r * PITCH + q * 4]) = make_float4(hh[0], hh[1], hh[2], hh[3]);
            *reinterpret_cast<float4*>(&Al[r * PITCH + q * 4]) = make_float4(ll[0], ll[1], ll[2], ll[3]);
        }
    };

    wmma::fragment<wmma::accumulator, 16, 16, 8, float> acc[4][2];
#pragma unroll
    for (int i = 0; i < 4; i++)
#pragma unroll
        for (int j = 0; j < 2; j++) wmma::fill_fragment(acc[i][j], 0.0f);

    // prologue
    if (!PRESPLIT_A) fetchA(0);
    issue(0, 0); CP_COMMIT();
    if (!PRESPLIT_A) storeA(0);
    CP_WAIT0();
    __syncthreads();

    for (int c = 0; c < C; c++) {
        const bool nxt = (c + 1 < C);
        if (nxt) {
            if (!PRESPLIT_A) fetchA((c + 1) * KC);
            issue((c + 1) * KC, (c + 1) & 1);
            CP_COMMIT();
        }
        const float* Ah = smf + (c & 1) * BUFF;
        const float* Al = Ah + ARRF;
        const float* Bh = Al + ARRF;
        const float* Bl = Bh + ARRF;
        const float* Awh = Ah + (wm * 64) * PITCH;
        const float* Awl = Al + (wm * 64) * PITCH;
        const float* Bwh = Bh + (wn * 32) * PITCH;
        const float* Bwl = Bl + (wn * 32) * PITCH;
#pragma unroll
        for (int ks = 0; ks < 2; ks++) {
            const int k0 = ks * 8;
            wmma::fragment<wmma::matrix_a, 16, 16, 8, wmma::precision::tf32, wmma::row_major> fah[4], fal[4];
            wmma::fragment<wmma::matrix_b, 16, 16, 8, wmma::precision::tf32, wmma::col_major> fbh[2], fbl[2];
#pragma unroll
            for (int i = 0; i < 4; i++) {
                wmma::load_matrix_sync(fah[i], Awh + (i * 16) * PITCH + k0, PITCH);
                wmma::load_matrix_sync(fal[i], Awl + (i * 16) * PITCH + k0, PITCH);
            }
#pragma unroll
            for (int j = 0; j < 2; j++) {
                wmma::load_matrix_sync(fbh[j], Bwh + (j * 16) * PITCH + k0, PITCH);
                wmma::load_matrix_sync(fbl[j], Bwl + (j * 16) * PITCH + k0, PITCH);
            }
#pragma unroll
            for (int i = 0; i < 4; i++)
#pragma unroll
                for (int j = 0; j < 2; j++) {
                    wmma::mma_sync(acc[i][j], fah[i], fbh[j], acc[i][j]);
                    wmma::mma_sync(acc[i][j], fal[i], fbh[j], acc[i][j]);
                    wmma::mma_sync(acc[i][j], fah[i], fbl[j], acc[i][j]);
                }
        }
        if (nxt && !PRESPLIT_A) storeA((c + 1) & 1);
        CP_WAIT0();
        __syncthreads();
    }

    // epilogue: stage in smem, fused bias + lrelu (+ optional tf32 split-out)
    constexpr int CP = 132;
    float* Cs = smf;
#pragma unroll
    for (int i = 0; i < 4; i++)
#pragma unroll
        for (int j = 0; j < 2; j++)
            wmma::store_matrix_sync(&Cs[(wm * 64 + i * 16) * CP + wn * 32 + j * 16],
                                    acc[i][j], CP, wmma::mem_row_major);
    __syncthreads();

#pragma unroll
    for (int it = 0; it < 16; it++) {
        int v = tid + it * 256;
        int r = v >> 5, c = (v & 31) * 4;
        float4 s = *reinterpret_cast<float4*>(&Cs[r * CP + c]);
        const float* bp = bias + col0 + c;
        s.x = lrelu(s.x + bp[0]);
        s.y = lrelu(s.y + bp[1]);
        s.z = lrelu(s.z + bp[2]);
        s.w = lrelu(s.w + bp[3]);
        const size_t o = (size_t)(row0 + r) * OutN + col0 + c;
        if (SPLIT_OUT) {
            float h0 = tf32r(s.x), h1 = tf32r(s.y), h2 = tf32r(s.z), h3 = tf32r(s.w);
            *reinterpret_cast<float4*>(&outH[o]) = make_float4(h0, h1, h2, h3);
            *reinterpret_cast<float4*>(&outL[o]) =
                make_float4(tf32r(s.x - h0), tf32r(s.y - h1), tf32r(s.z - h2), tf32r(s.w - h3));
        } else {
            *reinterpret_cast<float4*>(&outH[o]) = s;
        }
    }
}

// ============ prep: transpose + tf32-split weights ============
__global__ void prep_weights(const float* __restrict__ W1, const float* __restrict__ W2,
                             float* __restrict__ w1th, float* __restrict__ w1tl,
                             float* __restrict__ w2th, float* __restrict__ w2tl)
{
    int i = blockIdx.x * blockDim.x + threadIdx.x;
    if (i < 256 * 256) {
        int k = i >> 8, n = i & 255;
        float v = W1[i], h = tf32r(v);
        w1th[n * 256 + k] = h;
        w1tl[n * 256 + k] = tf32r(v - h);
    }
    if (i < 256 * 128) {
        int k = i >> 7, n = i & 127;
        float v = W2[i], h = tf32r(v);
        w2th[n * 256 + k] = h;
        w2tl[n * 256 + k] = tf32r(v - h);
    }
}

// ============ FFMA2 score kernel (L3, proven) ============
__device__ __forceinline__ unsigned long long lds64(const float* p) {
    unsigned long long v;
    unsigned a = (unsigned)__cvta_generic_to_shared(p);
    asm volatile("ld.shared.b64 %0, [%1];" : "=l"(v) : "r"(a));
    return v;
}
__device__ __forceinline__ void ffma2(unsigned long long& d, unsigned long long a,
                                      unsigned long long b) {
    asm volatile("fma.rn.f32x2 %0, %1, %2, %0;" : "+l"(d) : "l"(a), "l"(b));
}
__device__ __forceinline__ float2 up2(unsigned long long v) {
    float2 r;
    asm("mov.b64 {%0,%1}, %2;" : "=f"(r.x), "=f"(r.y) : "l"(v));
    return r;
}

template<int BN, int NT>
__global__ void __launch_bounds__(NT)
score_gemm(const float* __restrict__ A, const float* __restrict__ W,
           const float* __restrict__ bias, const float* __restrict__ w_atom,
           float* __restrict__ score_out, const int K, const int Ntot)
{
    constexpr int BM = 128, BK = 16, TM = 8, TN = 8;
    constexpr int TXN = BN / TN;
    constexpr int APITCH = BM + 4;
    constexpr int BPITCH = 2 * BN;
    constexpr int ASZ = BK * APITCH;
    constexpr int BSZ = BK * BPITCH;
    constexpr int A_IT = (BM * BK / 4) / NT;
    constexpr int B_IT = (BK * BN / 4) / NT;

    extern __shared__ float fsm[];
    float* Asm = fsm;
    float* Bsm = fsm + 2 * ASZ;
    float* sw  = Bsm + 2 * BSZ;

    const int tid = threadIdx.x;
    const int tx = tid % TXN;
    const int ty = tid / TXN;
    const int row0 = blockIdx.x * BM;

    if (tid < H3) sw[tid] = w_atom[tid];

    unsigned long long acc[4][8];
#pragma unroll
    for (int i = 0; i < 4; i++)
#pragma unroll
        for (int j = 0; j < 8; j++) acc[i][j] = 0ull;

    float4 ra[A_IT], rb[B_IT];
    auto fetchA = [&](int kt) {
#pragma unroll
        for (int i = 0; i < A_IT; i++) {
            int v = tid + i * NT, r = v >> 2, c4 = v & 3;
            ra[i] = *reinterpret_cast<const float4*>(&A[(size_t)(row0 + r) * K + kt + c4 * 4]);
        }
    };
    auto storeA = [&](int b) {
#pragma unroll
        for (int i = 0; i < A_IT; i++) {
            int v = tid + i * NT, r = v >> 2, c4 = v & 3;
            float* base = Asm + b * ASZ;
            base[(c4 * 4 + 0) * APITCH + r] = ra[i].x;
            base[(c4 * 4 + 1) * APITCH + r] = ra[i].y;
            base[(c4 * 4 + 2) * APITCH + r] = ra[i].z;
            base[(c4 * 4 + 3) * APITCH + r] = ra[i].w;
        }
    };
    auto fetchB = [&](int kt) {
#pragma unroll
        for (int i = 0; i < B_IT; i++) {
            int v = tid + i * NT, kr = v / (BN / 4), c4 = v % (BN / 4);
            rb[i] = *reinterpret_cast<const float4*>(&W[(size_t)(kt + kr) * Ntot + c4 * 4]);
        }
    };
    auto storeB = [&](int b) {
#pragma unroll
        for (int i = 0; i < B_IT; i++) {
            int v = tid + i * NT, kr = v / (BN / 4), c4 = v % (BN / 4);
            float* base = Bsm + b * BSZ + kr * BPITCH;
            float vv[4] = {rb[i].x, rb[i].y, rb[i].z, rb[i].w};
#pragma unroll
            for (int j = 0; j < 4; j++) {
                int col = c4 * 4 + j;
                int addr = (col % TN) * (2 * TXN) + 2 * (col / TN);
                *reinterpret_cast<float2*>(&base[addr]) = make_float2(vv[j], vv[j]);
            }
        }
    };

    fetchA(0); fetchB(0);
    storeA(0); storeB(0);
    __syncthreads();
    int buf = 0;
    for (int kt = 0; kt < K; kt += BK) {
        const bool nxt = (kt + BK < K);
        if (nxt) { fetchA(kt + BK); fetchB(kt + BK); }
        const float* Ab = Asm + buf * ASZ + ty * TM;
        const float* Bb = Bsm + buf * BSZ + 2 * tx;
#pragma unroll
        for (int k = 0; k < BK; k++) {
            unsigned long long ap[4], bp[8];
#pragma unroll
            for (int m = 0; m < 4; m++) ap[m] = lds64(Ab + k * APITCH + 2 * m);
#pragma unroll
            for (int n = 0; n < 8; n++) bp[n] = lds64(Bb + k * BPITCH + n * (2 * TXN));
#pragma unroll
            for (int m = 0; m < 4; m++)
#pragma unroll
                for (int n = 0; n < 8; n++) ffma2(acc[m][n], ap[m], bp[n]);
        }
        if (nxt) { storeA(buf ^ 1); storeB(buf ^ 1); }
        __syncthreads();
        buf ^= 1;
    }

    float wn = 0.f;
#pragma unroll
    for (int j = 0; j < H3; j++) wn += sw[j] * sw[j];
    const float nrm = sqrtf(wn);
    float bb[8], wa[8];
#pragma unroll
    for (int n = 0; n < 8; n++) { bb[n] = bias[tx * TN + n]; wa[n] = sw[tx * TN + n]; }
#pragma unroll
    for (int mp = 0; mp < 4; mp++) {
        float p0 = 0.f, p1 = 0.f;
#pragma unroll
        for (int n = 0; n < 8; n++) {
            float2 t = up2(acc[mp][n]);
            p0 += lrelu(t.x + bb[n]) * wa[n];
            p1 += lrelu(t.y + bb[n]) * wa[n];
        }
#pragma unroll
        for (int o = 1; o < TXN; o <<= 1) {
            p0 += __shfl_xor_sync(0xffffffffu, p0, o);
            p1 += __shfl_xor_sync(0xffffffffu, p1, o);
        }
        if (tx == 0) {
            int r = row0 + ty * TM + mp * 2;
            score_out[r]     = tanhf(p0 / nrm);
            score_out[r + 1] = tanhf(p1 / nrm);
        }
    }
}

// ============ topk + gather (proven) ============
__global__ void topk_gather(const float* __restrict__ x, const float* __restrict__ pe,
                            const float* __restrict__ score,
                            const int* __restrict__ on_index,
                            float* __restrict__ out, const long long out_size)
{
    __shared__ float s[NPG];
    __shared__ int pos[NPG];
    __shared__ int sel[KSEL];
    const int g = blockIdx.x;
    const int tid = threadIdx.x;
    s[tid] = score[g * NPG + tid];
    __syncthreads();
    const float my = s[tid];
    int r = 0;
#pragma unroll 8
    for (int j = 0; j < NPG; j++) {
        float v = s[j];
        r += (v > my) || (v == my && j < tid);
    }
    pos[r] = tid;
    __syncthreads();
    if (tid == 0) {
        int c = 0;
        for (int rr = 0; rr < NPG && c < KSEL; rr++) {
            int node = pos[rr];
            if ((node & 1) == 0) sel[c++] = node;
        }
    }
    __syncthreads();

    const long long OFF_PERM = (long long)NGRAPH * KSEL * CIN;
    const long long OFF_SCON = OFF_PERM + (long long)NGRAPH * KSEL;
    const long long OFF_ONIX = OFF_SCON + (long long)NGRAPH * ONPG;
    const long long TOTAL    = OFF_ONIX + (long long)NGRAPH * ONPG;

    for (int idx = tid; idx < KSEL * CIN; idx += blockDim.x) {
        int c = idx >> 8;
        int ch = idx & (CIN - 1);
        int node = sel[c];
        size_t gn = (size_t)g * NPG + node;
        float xp = x[gn * CIN + ch] + pe[(size_t)node * CIN + ch];
        out[((size_t)g * KSEL + c) * CIN + ch] = xp * s[node];
    }
    if (out_size >= TOTAL) {
        if (tid < KSEL)
            out[OFF_PERM + g * KSEL + tid] = (float)(g * NPG + sel[tid]);
        if (tid < ONPG) {
            int oi = on_index[g * ONPG + tid];
            out[OFF_SCON + g * ONPG + tid] = s[oi - g * NPG];
            out[OFF_ONIX + g * ONPG + tid] = (float)oi;
        }
    }
}

// ============ launch ============
extern "C" void kernel_launch(void* const* d_in, const int* in_sizes, int n_in,
                              void* d_out, int out_size)
{
    const float* x      = (const float*)d_in[0];
    const float* pe     = (const float*)d_in[1];
    const float* W1     = (const float*)d_in[2];
    const float* b1     = (const float*)d_in[3];
    const float* W2     = (const float*)d_in[4];
    const float* b2     = (const float*)d_in[5];
    const float* W3     = (const float*)d_in[6];
    const float* b3     = (const float*)d_in[7];
    const float* w_atom = (const float*)d_in[8];
    const int*   on_idx = (const int*)d_in[10];
    float* out = (float*)d_out;

    float *h1h, *h1l, *h2, *sc, *w1th, *w1tl, *w2th, *w2tl;
    cudaGetSymbolAddress((void**)&h1h, g_h1h);
    cudaGetSymbolAddress((void**)&h1l, g_h1l);
    cudaGetSymbolAddress((void**)&h2, g_h2);
    cudaGetSymbolAddress((void**)&sc, g_score);
    cudaGetSymbolAddress((void**)&w1th, g_w1th);
    cudaGetSymbolAddress((void**)&w1tl, g_w1tl);
    cudaGetSymbolAddress((void**)&w2th, g_w2th);
    cudaGetSymbolAddress((void**)&w2tl, g_w2tl);

    const int SMG = 81920;                                         // gemm dyn smem
    const int smemS = (2 * 16 * 132 + 2 * 16 * 128 + 64) * 4;      // score kernel

    static bool attr_done = false;
    if (!attr_done) {
        cudaFuncSetAttribute(tf32cp_gemm<false, true>,
                             cudaFuncAttributeMaxDynamicSharedMemorySize, SMG);
        cudaFuncSetAttribute(tf32cp_gemm<true, false>,
                             cudaFuncAttributeMaxDynamicSharedMemorySize, SMG);
        cudaFuncSetAttribute(score_gemm<64, 128>,
                             cudaFuncAttributeMaxDynamicSharedMemorySize, smemS);
        attr_done = true;
    }

    prep_weights<<<256, 256>>>(W1, W2, w1th, w1tl, w2th, w2tl);
    // L1: h1(split) = lrelu((x+pe) @ W1 + b1)
    tf32cp_gemm<false, true><<<dim3(512, 2), 256, SMG>>>(
        x, pe, nullptr, nullptr, w1th, w1tl, b1, h1h, h1l, 256, 256);
    // L2: h2 = lrelu(h1 @ W2 + b2)
    tf32cp_gemm<true, false><<<dim3(512, 1), 256, SMG>>>(
        nullptr, nullptr, h1h, h1l, w2th, w2tl, b2, h2, nullptr, 256, 128);
    // L3 + score
    score_gemm<64, 128><<<512, 128, smemS>>>(h2, W3, b3, w_atom, sc, 128, 64);
    // rank + select + gather
    topk_gather<<<NGRAPH, NPG>>>(x, pe, sc, on_idx, out, (long long)out_size);
}

// round 6
// speedup vs baseline: 1.3410x; 1.3410x over previous
#include <cuda_runtime.h>
#include <math.h>
#include <stdint.h>

#define NNODES 65536
#define NGRAPH 256
#define NPG    256
#define CIN    256
#define KSEL   16
#define ONPG   128
#define H3     64

__device__ float g_h1[(size_t)NNODES * 256];
__device__ float g_h2[(size_t)NNODES * 128];
__device__ float g_score[NNODES];

__device__ __forceinline__ unsigned long long lds64(const float* p) {
    unsigned long long v;
    unsigned a = (unsigned)__cvta_generic_to_shared(p);
    asm volatile("ld.shared.b64 %0, [%1];" : "=l"(v) : "r"(a));
    return v;
}
__device__ __forceinline__ void ffma2(unsigned long long& d, unsigned long long a,
                                      unsigned long long b) {
    asm volatile("fma.rn.f32x2 %0, %1, %2, %0;" : "+l"(d) : "l"(a), "l"(b));
}
__device__ __forceinline__ float2 up2(unsigned long long v) {
    float2 r;
    asm("mov.b64 {%0,%1}, %2;" : "=f"(r.x), "=f"(r.y) : "l"(v));
    return r;
}
__device__ __forceinline__ void sts_v2(float* p, float a, float b) {
    unsigned ad = (unsigned)__cvta_generic_to_shared(p);
    asm volatile("st.shared.v2.f32 [%0], {%1, %2};" :: "r"(ad), "f"(a), "f"(b) : "memory");
}
__device__ __forceinline__ float lrelu(float z) { return z > 0.0f ? z : 0.1f * z; }

// ==================== N-paired FFMA2 GEMM: out = lrelu(A @ W + b) ====================
// A [M,K] fp32 row-major, W [K,OutN] fp32 row-major (natural, no transpose).
// CTA tile 128(M) x 128(N), BK=16, 256 threads. Thread tile 8x8, cols paired.
// A in smem transposed+duplicated [k][2m]=[k][2m+1]=a(m); B pair-interleaved so
// the inner-loop LDS.64 b-fetch hits all 32 banks exactly once (conflict-free).
template<bool ADD_PE>
__global__ void __launch_bounds__(256)
npair_gemm(const float* __restrict__ A, const float* __restrict__ W,
           const float* __restrict__ bias, const float* __restrict__ pe,
           float* __restrict__ out, const int K, const int OutN)
{
    constexpr int BM = 128, BN = 128, BK = 16, NT = 256;
    constexpr int APITCH = 260;            // floats per k-row (256 dup + 4 pad)
    constexpr int BPITCH = 136;            // floats per k-row (128 + 8 pad)
    constexpr int ASZ = BK * APITCH;       // 4160
    constexpr int BSZ = BK * BPITCH;       // 2176

    extern __shared__ float smf[];
    float* Asm = smf;                      // [2][ASZ]
    float* Bsm = smf + 2 * ASZ;            // [2][BSZ]

    const int tid = threadIdx.x;
    const int tx = tid & 15;               // col group: cols tx*8 .. +7
    const int ty = tid >> 4;               // row group: rows ty*8 .. +7
    const int row0 = blockIdx.x * BM;
    const int col0 = blockIdx.y * BN;

    unsigned long long acc[8][4];          // acc[m][p] = (col 2p, col 2p+1) of row m
#pragma unroll
    for (int m = 0; m < 8; m++)
#pragma unroll
        for (int p = 0; p < 4; p++) acc[m][p] = 0ull;

    float4 ra[2], rp[2], rb[2];
    auto fetchA = [&](int kt) {
#pragma unroll
        for (int i = 0; i < 2; i++) {
            int v = tid + i * NT, r = v >> 2, c4 = v & 3;
            ra[i] = *reinterpret_cast<const float4*>(&A[(size_t)(row0 + r) * K + kt + c4 * 4]);
            if (ADD_PE)
                rp[i] = *reinterpret_cast<const float4*>(
                    &pe[(size_t)((row0 + r) & (NPG - 1)) * CIN + kt + c4 * 4]);
        }
    };
    auto storeA = [&](int b) {
        float* base = Asm + b * ASZ;
#pragma unroll
        for (int i = 0; i < 2; i++) {
            int v = tid + i * NT, r = v >> 2, c4 = v & 3;
            float av[4] = {ra[i].x, ra[i].y, ra[i].z, ra[i].w};
            if (ADD_PE) { av[0] += rp[i].x; av[1] += rp[i].y; av[2] += rp[i].z; av[3] += rp[i].w; }
#pragma unroll
            for (int j = 0; j < 4; j++)
                sts_v2(&base[(c4 * 4 + j) * APITCH + 2 * r], av[j], av[j]);
        }
    };
    auto fetchB = [&](int kt) {
#pragma unroll
        for (int i = 0; i < 2; i++) {
            int v = tid + i * NT, kr = v >> 5, c4 = v & 31;
            rb[i] = *reinterpret_cast<const float4*>(
                &W[(size_t)(kt + kr) * OutN + col0 + c4 * 4]);
        }
    };
    auto storeB = [&](int b) {
        float* base = Bsm + b * BSZ;
#pragma unroll
        for (int i = 0; i < 2; i++) {
            int v = tid + i * NT, kr = v >> 5, c4 = v & 31;
            int q0 = 2 * c4, q1 = 2 * c4 + 1;
            int f0 = (q0 & 3) * 32 + (q0 >> 2) * 2;
            int f1 = (q1 & 3) * 32 + (q1 >> 2) * 2;
            sts_v2(&base[kr * BPITCH + f0], rb[i].x, rb[i].y);
            sts_v2(&base[kr * BPITCH + f1], rb[i].z, rb[i].w);
        }
    };

    fetchA(0); fetchB(0);
    storeA(0); storeB(0);
    __syncthreads();

    int buf = 0;
    for (int kt = 0; kt < K; kt += BK) {
        const bool nxt = (kt + BK < K);
        if (nxt) { fetchA(kt + BK); fetchB(kt + BK); }
        const float* Ab = Asm + buf * ASZ + ty * 16;    // 2*(ty*8)
        const float* Bb = Bsm + buf * BSZ + tx * 2;
#pragma unroll
        for (int k = 0; k < BK; k++) {
            unsigned long long ap[8], bp[4];
#pragma unroll
            for (int m = 0; m < 8; m++) ap[m] = lds64(Ab + k * APITCH + 2 * m);
#pragma unroll
            for (int p = 0; p < 4; p++) bp[p] = lds64(Bb + k * BPITCH + p * 32);
#pragma unroll
            for (int m = 0; m < 8; m++)
#pragma unroll
                for (int p = 0; p < 4; p++) ffma2(acc[m][p], ap[m], bp[p]);
        }
        if (nxt) { storeA(buf ^ 1); storeB(buf ^ 1); }
        __syncthreads();
        buf ^= 1;
    }

    // Epilogue: acc[m][p] holds contiguous col pairs -> two float4 stores per row.
    float bb[8];
#pragma unroll
    for (int n = 0; n < 8; n++) bb[n] = bias[col0 + tx * 8 + n];
#pragma unroll
    for (int m = 0; m < 8; m++) {
        float vv[8];
#pragma unroll
        for (int p = 0; p < 4; p++) {
            float2 t = up2(acc[m][p]);
            vv[2 * p]     = lrelu(t.x + bb[2 * p]);
            vv[2 * p + 1] = lrelu(t.y + bb[2 * p + 1]);
        }
        float* op = out + (size_t)(row0 + ty * 8 + m) * OutN + col0 + tx * 8;
        *reinterpret_cast<float4*>(op)     = make_float4(vv[0], vv[1], vv[2], vv[3]);
        *reinterpret_cast<float4*>(op + 4) = make_float4(vv[4], vv[5], vv[6], vv[7]);
    }
}

// ==================== FFMA2 score kernel (L3, proven R2) ====================
template<int BN, int NT>
__global__ void __launch_bounds__(NT)
score_gemm(const float* __restrict__ A, const float* __restrict__ W,
           const float* __restrict__ bias, const float* __restrict__ w_atom,
           float* __restrict__ score_out, const int K, const int Ntot)
{
    constexpr int BM = 128, BK = 16, TM = 8, TN = 8;
    constexpr int TXN = BN / TN;
    constexpr int APITCH = BM + 4;
    constexpr int BPITCH = 2 * BN;
    constexpr int ASZ = BK * APITCH;
    constexpr int BSZ = BK * BPITCH;
    constexpr int A_IT = (BM * BK / 4) / NT;
    constexpr int B_IT = (BK * BN / 4) / NT;

    extern __shared__ float fsm[];
    float* Asm = fsm;
    float* Bsm = fsm + 2 * ASZ;
    float* sw  = Bsm + 2 * BSZ;

    const int tid = threadIdx.x;
    const int tx = tid % TXN;
    const int ty = tid / TXN;
    const int row0 = blockIdx.x * BM;

    if (tid < H3) sw[tid] = w_atom[tid];

    unsigned long long acc[4][8];
#pragma unroll
    for (int i = 0; i < 4; i++)
#pragma unroll
        for (int j = 0; j < 8; j++) acc[i][j] = 0ull;

    float4 ra[A_IT], rb[B_IT];
    auto fetchA = [&](int kt) {
#pragma unroll
        for (int i = 0; i < A_IT; i++) {
            int v = tid + i * NT, r = v >> 2, c4 = v & 3;
            ra[i] = *reinterpret_cast<const float4*>(&A[(size_t)(row0 + r) * K + kt + c4 * 4]);
        }
    };
    auto storeA = [&](int b) {
#pragma unroll
        for (int i = 0; i < A_IT; i++) {
            int v = tid + i * NT, r = v >> 2, c4 = v & 3;
            float* base = Asm + b * ASZ;
            base[(c4 * 4 + 0) * APITCH + r] = ra[i].x;
            base[(c4 * 4 + 1) * APITCH + r] = ra[i].y;
            base[(c4 * 4 + 2) * APITCH + r] = ra[i].z;
            base[(c4 * 4 + 3) * APITCH + r] = ra[i].w;
        }
    };
    auto fetchB = [&](int kt) {
#pragma unroll
        for (int i = 0; i < B_IT; i++) {
            int v = tid + i * NT, kr = v / (BN / 4), c4 = v % (BN / 4);
            rb[i] = *reinterpret_cast<const float4*>(&W[(size_t)(kt + kr) * Ntot + c4 * 4]);
        }
    };
    auto storeB = [&](int b) {
#pragma unroll
        for (int i = 0; i < B_IT; i++) {
            int v = tid + i * NT, kr = v / (BN / 4), c4 = v % (BN / 4);
            float* base = Bsm + b * BSZ + kr * BPITCH;
            float vv[4] = {rb[i].x, rb[i].y, rb[i].z, rb[i].w};
#pragma unroll
            for (int j = 0; j < 4; j++) {
                int col = c4 * 4 + j;
                int addr = (col % TN) * (2 * TXN) + 2 * (col / TN);
                *reinterpret_cast<float2*>(&base[addr]) = make_float2(vv[j], vv[j]);
            }
        }
    };

    fetchA(0); fetchB(0);
    storeA(0); storeB(0);
    __syncthreads();
    int buf = 0;
    for (int kt = 0; kt < K; kt += BK) {
        const bool nxt = (kt + BK < K);
        if (nxt) { fetchA(kt + BK); fetchB(kt + BK); }
        const float* Ab = Asm + buf * ASZ + ty * TM;
        const float* Bb = Bsm + buf * BSZ + 2 * tx;
#pragma unroll
        for (int k = 0; k < BK; k++) {
            unsigned long long ap[4], bp[8];
#pragma unroll
            for (int m = 0; m < 4; m++) ap[m] = lds64(Ab + k * APITCH + 2 * m);
#pragma unroll
            for (int n = 0; n < 8; n++) bp[n] = lds64(Bb + k * BPITCH + n * (2 * TXN));
#pragma unroll
            for (int m = 0; m < 4; m++)
#pragma unroll
                for (int n = 0; n < 8; n++) ffma2(acc[m][n], ap[m], bp[n]);
        }
        if (nxt) { storeA(buf ^ 1); storeB(buf ^ 1); }
        __syncthreads();
        buf ^= 1;
    }

    float wn = 0.f;
#pragma unroll
    for (int j = 0; j < H3; j++) wn += sw[j] * sw[j];
    const float nrm = sqrtf(wn);
    float bb[8], wa[8];
#pragma unroll
    for (int n = 0; n < 8; n++) { bb[n] = bias[tx * TN + n]; wa[n] = sw[tx * TN + n]; }
#pragma unroll
    for (int mp = 0; mp < 4; mp++) {
        float p0 = 0.f, p1 = 0.f;
#pragma unroll
        for (int n = 0; n < 8; n++) {
            float2 t = up2(acc[mp][n]);
            p0 += lrelu(t.x + bb[n]) * wa[n];
            p1 += lrelu(t.y + bb[n]) * wa[n];
        }
#pragma unroll
        for (int o = 1; o < TXN; o <<= 1) {
            p0 += __shfl_xor_sync(0xffffffffu, p0, o);
            p1 += __shfl_xor_sync(0xffffffffu, p1, o);
        }
        if (tx == 0) {
            int r = row0 + ty * TM + mp * 2;
            score_out[r]     = tanhf(p0 / nrm);
            score_out[r + 1] = tanhf(p1 / nrm);
        }
    }
}

// ==================== topk + gather (proven) ====================
__global__ void topk_gather(const float* __restrict__ x, const float* __restrict__ pe,
                            const float* __restrict__ score,
                            const int* __restrict__ on_index,
                            float* __restrict__ out, const long long out_size)
{
    __shared__ float s[NPG];
    __shared__ int pos[NPG];
    __shared__ int sel[KSEL];
    const int g = blockIdx.x;
    const int tid = threadIdx.x;
    s[tid] = score[g * NPG + tid];
    __syncthreads();
    const float my = s[tid];
    int r = 0;
#pragma unroll 8
    for (int j = 0; j < NPG; j++) {
        float v = s[j];
        r += (v > my) || (v == my && j < tid);
    }
    pos[r] = tid;
    __syncthreads();
    if (tid == 0) {
        int c = 0;
        for (int rr = 0; rr < NPG && c < KSEL; rr++) {
            int node = pos[rr];
            if ((node & 1) == 0) sel[c++] = node;
        }
    }
    __syncthreads();

    const long long OFF_PERM = (long long)NGRAPH * KSEL * CIN;
    const long long OFF_SCON = OFF_PERM + (long long)NGRAPH * KSEL;
    const long long OFF_ONIX = OFF_SCON + (long long)NGRAPH * ONPG;
    const long long TOTAL    = OFF_ONIX + (long long)NGRAPH * ONPG;

    for (int idx = tid; idx < KSEL * CIN; idx += blockDim.x) {
        int c = idx >> 8;
        int ch = idx & (CIN - 1);
        int node = sel[c];
        size_t gn = (size_t)g * NPG + node;
        float xp = x[gn * CIN + ch] + pe[(size_t)node * CIN + ch];
        out[((size_t)g * KSEL + c) * CIN + ch] = xp * s[node];
    }
    if (out_size >= TOTAL) {
        if (tid < KSEL)
            out[OFF_PERM + g * KSEL + tid] = (float)(g * NPG + sel[tid]);
        if (tid < ONPG) {
            int oi = on_index[g * ONPG + tid];
            out[OFF_SCON + g * ONPG + tid] = s[oi - g * NPG];
            out[OFF_ONIX + g * ONPG + tid] = (float)oi;
        }
    }
}

// ==================== launch ====================
extern "C" void kernel_launch(void* const* d_in, const int* in_sizes, int n_in,
                              void* d_out, int out_size)
{
    const float* x      = (const float*)d_in[0];
    const float* pe     = (const float*)d_in[1];
    const float* W1     = (const float*)d_in[2];
    const float* b1     = (const float*)d_in[3];
    const float* W2     = (const float*)d_in[4];
    const float* b2     = (const float*)d_in[5];
    const float* W3     = (const float*)d_in[6];
    const float* b3     = (const float*)d_in[7];
    const float* w_atom = (const float*)d_in[8];
    const int*   on_idx = (const int*)d_in[10];
    float* out = (float*)d_out;

    float *h1, *h2, *sc;
    cudaGetSymbolAddress((void**)&h1, g_h1);
    cudaGetSymbolAddress((void**)&h2, g_h2);
    cudaGetSymbolAddress((void**)&sc, g_score);

    const int SMG   = 2 * (16 * 260 + 16 * 136) * 4;              // 50688 B
    const int smemS = (2 * 16 * 132 + 2 * 16 * 128 + 64) * 4;     // score kernel

    static bool attr_done = false;
    if (!attr_done) {
        cudaFuncSetAttribute(npair_gemm<true>,
                             cudaFuncAttributeMaxDynamicSharedMemorySize, SMG);
        cudaFuncSetAttribute(npair_gemm<false>,
                             cudaFuncAttributeMaxDynamicSharedMemorySize, SMG);
        cudaFuncSetAttribute(score_gemm<64, 128>,
                             cudaFuncAttributeMaxDynamicSharedMemorySize, smemS);
        attr_done = true;
    }

    // L1: h1 = lrelu((x+pe) @ W1 + b1)   [65536,256] x [256,256]
    npair_gemm<true><<<dim3(512, 2), 256, SMG>>>(x, W1, b1, pe, h1, 256, 256);
    // L2: h2 = lrelu(h1 @ W2 + b2)       [65536,256] x [256,128]
    npair_gemm<false><<<dim3(512, 1), 256, SMG>>>(h1, W2, b2, nullptr, h2, 256, 128);
    // L3 + score
    score_gemm<64, 128><<<512, 128, smemS>>>(h2, W3, b3, w_atom, sc, 128, 64);
    // rank + select + gather
    topk_gather<<<NGRAPH, NPG>>>(x, pe, sc, on_idx, out, (long long)out_size);
}

// round 7
// speedup vs baseline: 2.6159x; 1.9506x over previous
#include <cuda_runtime.h>
#include <cuda_fp16.h>
#include <mma.h>
#include <math.h>
#include <stdint.h>

using namespace nvcuda;

#define NNODES 65536
#define NGRAPH 256
#define NPG    256
#define CIN    256
#define KSEL   16
#define ONPG   128
#define H3     64

// scratch (device globals; allocations forbidden)
__device__ __half g_h1h[(size_t)NNODES * 256];
__device__ __half g_h1l[(size_t)NNODES * 256];
__device__ float  g_h2[(size_t)NNODES * 128];
__device__ float  g_score[NNODES];
__device__ __half g_w1h[256 * 256], g_w1l[256 * 256];   // W1 [K][N] fp16 split
__device__ __half g_w2h[256 * 128], g_w2l[256 * 128];   // W2 [K][N] fp16 split

__device__ __forceinline__ float lrelu(float z) { return z > 0.0f ? z : 0.1f * z; }
__device__ __forceinline__ uint32_t smem_u32(const void* p) {
    uint32_t a;
    asm("{ .reg .u64 t; cvta.to.shared.u64 t, %1; cvt.u32.u64 %0, t; }" : "=r"(a) : "l"(p));
    return a;
}
__device__ __forceinline__ void cp16(uint32_t dst, const void* src) {
    asm volatile("cp.async.cg.shared.global [%0], [%1], 16;" :: "r"(dst), "l"(src));
}
#define CP_COMMIT() asm volatile("cp.async.commit_group;" ::: "memory")
#define CP_WAIT0()  asm volatile("cp.async.wait_group 0;" ::: "memory")

__device__ __forceinline__ uint32_t packh2(__half a, __half b) {
    return (uint32_t)__half_as_ushort(a) | ((uint32_t)__half_as_ushort(b) << 16);
}
__device__ __forceinline__ void sts16(uint32_t addr, uint32_t a, uint32_t b,
                                      uint32_t c, uint32_t d) {
    asm volatile("st.shared.v4.b32 [%0], {%1,%2,%3,%4};"
                 :: "r"(addr), "r"(a), "r"(b), "r"(c), "r"(d) : "memory");
}

// ========== fp16 3-split GEMM: out = lrelu(A @ W + bias) ==========
// A [M,K]: raw fp32 (+pe) split in-kernel, or pre-split fp16 hi/lo.
// W [K,N] pre-split fp16 hi/lo (natural layout, row-major B fragments).
// CTA 128x128, KC=32, 512 threads = 16 warps (4m x 4n), warp tile 32x32.
template<bool PRESPLIT_A, bool SPLIT_OUT>
__global__ void __launch_bounds__(512)
hsplit_gemm(const float* __restrict__ Araw, const float* __restrict__ pe,
            const __half* __restrict__ AhG, const __half* __restrict__ AlG,
            const __half* __restrict__ BhG, const __half* __restrict__ BlG,
            const float* __restrict__ bias,
            float* __restrict__ outF, __half* __restrict__ outH, __half* __restrict__ outL,
            const int K, const int OutN)
{
    constexpr int KC = 32;
    constexpr int APITCH = 40;                 // halves per A row (32 + 8 pad)
    constexpr int BPITCH = 136;                // halves per B k-row (128 + 8 pad)
    constexpr int ASZ = 128 * APITCH;          // 5120 halves per split
    constexpr int BSZ = KC * BPITCH;           // 4352 halves per split
    constexpr int BUFH = 2 * ASZ + 2 * BSZ;    // 18944 halves per buffer

    extern __shared__ __half smh[];
    const uint32_t sb = smem_u32(smh);

    const int tid = threadIdx.x;
    const int wid = tid >> 5;
    const int wm = wid >> 2;                   // 0..3
    const int wn = wid & 3;                    // 0..3
    const int row0 = blockIdx.x * 128;
    const int col0 = blockIdx.y * 128;
    const int C = K / KC;

    // cp.async: B splits always (32 rows x 256B each); A splits if presplit (128 x 64B)
    auto issue = [&](int kt, int b) {
        const uint32_t d0 = sb + (uint32_t)b * (BUFH * 2u);
        {   // B: v = tid (512 = 32 rows * 16 chunks)
            int kr = tid >> 4, cc = tid & 15;
            const uint32_t so = (uint32_t)(kr * BPITCH + cc * 8) * 2u;
            const size_t g = (size_t)(kt + kr) * OutN + col0 + cc * 8;
            cp16(d0 + 2u * ASZ * 2u + so, BhG + g);
            cp16(d0 + (2u * ASZ + BSZ) * 2u + so, BlG + g);
        }
        if (PRESPLIT_A) {   // A: 128 rows * 4 chunks
            int r = tid >> 2, cc = tid & 3;
            const uint32_t so = (uint32_t)(r * APITCH + cc * 8) * 2u;
            const size_t g = (size_t)(row0 + r) * K + kt + cc * 8;
            cp16(d0 + so, AhG + g);
            cp16(d0 + ASZ * 2u + so, AlG + g);
        }
    };

    float4 fa[2], fp[2];
    auto fetchA = [&](int kt) {                // L1: 8 floats per thread
        int r = tid >> 2, q = tid & 3;
#pragma unroll
        for (int i = 0; i < 2; i++) {
            fa[i] = *reinterpret_cast<const float4*>(&Araw[(size_t)(row0 + r) * K + kt + q * 8 + i * 4]);
            fp[i] = *reinterpret_cast<const float4*>(&pe[(size_t)((row0 + r) & (NPG - 1)) * CIN + kt + q * 8 + i * 4]);
        }
    };
    auto storeA = [&](int b) {
        int r = tid >> 2, q = tid & 3;
        float v[8] = {fa[0].x + fp[0].x, fa[0].y + fp[0].y, fa[0].z + fp[0].z, fa[0].w + fp[0].w,
                      fa[1].x + fp[1].x, fa[1].y + fp[1].y, fa[1].z + fp[1].z, fa[1].w + fp[1].w};
        __half hh[8], ll[8];
#pragma unroll
        for (int j = 0; j < 8; j++) {
            hh[j] = __float2half_rn(v[j]);
            ll[j] = __float2half_rn(v[j] - __half2float(hh[j]));
        }
        const uint32_t d0 = sb + (uint32_t)b * (BUFH * 2u);
        const uint32_t so = (uint32_t)(r * APITCH + q * 8) * 2u;
        sts16(d0 + so, packh2(hh[0], hh[1]), packh2(hh[2], hh[3]),
                       packh2(hh[4], hh[5]), packh2(hh[6], hh[7]));
        sts16(d0 + ASZ * 2u + so, packh2(ll[0], ll[1]), packh2(ll[2], ll[3]),
                                  packh2(ll[4], ll[5]), packh2(ll[6], ll[7]));
    };

    wmma::fragment<wmma::accumulator, 16, 16, 16, float> acc[2][2];
#pragma unroll
    for (int i = 0; i < 2; i++)
#pragma unroll
        for (int j = 0; j < 2; j++) wmma::fill_fragment(acc[i][j], 0.0f);

    // prologue
    if (!PRESPLIT_A) fetchA(0);
    issue(0, 0); CP_COMMIT();
    if (!PRESPLIT_A) storeA(0);
    CP_WAIT0();
    __syncthreads();

    for (int c = 0; c < C; c++) {
        const bool nxt = (c + 1 < C);
        if (nxt) {
            if (!PRESPLIT_A) fetchA((c + 1) * KC);
            issue((c + 1) * KC, (c + 1) & 1);
            CP_COMMIT();
        }
        const __half* Ah = smh + (c & 1) * BUFH;
        const __half* Al = Ah + ASZ;
        const __half* Bh = Al + ASZ;
        const __half* Bl = Bh + BSZ;
#pragma unroll
        for (int ks = 0; ks < 2; ks++) {
            const int k0 = ks * 16;
            wmma::fragment<wmma::matrix_b, 16, 16, 16, __half, wmma::row_major> fbh[2], fbl[2];
#pragma unroll
            for (int j = 0; j < 2; j++) {
                wmma::load_matrix_sync(fbh[j], Bh + k0 * BPITCH + wn * 32 + j * 16, BPITCH);
                wmma::load_matrix_sync(fbl[j], Bl + k0 * BPITCH + wn * 32 + j * 16, BPITCH);
            }
#pragma unroll
            for (int i = 0; i < 2; i++) {
                wmma::fragment<wmma::matrix_a, 16, 16, 16, __half, wmma::row_major> fah, fal;
                wmma::load_matrix_sync(fah, Ah + (wm * 32 + i * 16) * APITCH + k0, APITCH);
                wmma::load_matrix_sync(fal, Al + (wm * 32 + i * 16) * APITCH + k0, APITCH);
#pragma unroll
                for (int j = 0; j < 2; j++) {
                    wmma::mma_sync(acc[i][j], fah, fbh[j], acc[i][j]);
                    wmma::mma_sync(acc[i][j], fal, fbh[j], acc[i][j]);
                    wmma::mma_sync(acc[i][j], fah, fbl[j], acc[i][j]);
                }
            }
        }
        if (nxt && !PRESPLIT_A) storeA((c + 1) & 1);
        CP_WAIT0();
        __syncthreads();
    }

    // epilogue: stage fp32 C in smem, fused bias+lrelu, optional fp16 split-out
    constexpr int CP = 132;
    float* Cs = reinterpret_cast<float*>(smh);
#pragma unroll
    for (int i = 0; i < 2; i++)
#pragma unroll
        for (int j = 0; j < 2; j++)
            wmma::store_matrix_sync(&Cs[(wm * 32 + i * 16) * CP + wn * 32 + j * 16],
                                    acc[i][j], CP, wmma::mem_row_major);
    __syncthreads();

#pragma unroll
    for (int it = 0; it < 8; it++) {
        int v = tid + it * 512;
        int r = v >> 5, cc = (v & 31) * 4;
        float4 s = *reinterpret_cast<float4*>(&Cs[r * CP + cc]);
        const float* bp = bias + col0 + cc;
        s.x = lrelu(s.x + bp[0]);
        s.y = lrelu(s.y + bp[1]);
        s.z = lrelu(s.z + bp[2]);
        s.w = lrelu(s.w + bp[3]);
        const size_t o = (size_t)(row0 + r) * OutN + col0 + cc;
        if (SPLIT_OUT) {
            __half h0 = __float2half_rn(s.x), h1 = __float2half_rn(s.y);
            __half h2v = __float2half_rn(s.z), h3 = __float2half_rn(s.w);
            *reinterpret_cast<__half2*>(outH + o)     = __halves2half2(h0, h1);
            *reinterpret_cast<__half2*>(outH + o + 2) = __halves2half2(h2v, h3);
            *reinterpret_cast<__half2*>(outL + o) = __halves2half2(
                __float2half_rn(s.x - __half2float(h0)), __float2half_rn(s.y - __half2float(h1)));
            *reinterpret_cast<__half2*>(outL + o + 2) = __halves2half2(
                __float2half_rn(s.z - __half2float(h2v)), __float2half_rn(s.w - __half2float(h3)));
        } else {
            *reinterpret_cast<float4*>(&outF[o]) = s;
        }
    }
}

// ========== prep: fp16-split weights (natural [K][N] layout) ==========
__global__ void prep_weights(const float* __restrict__ W1, const float* __restrict__ W2,
                             __half* __restrict__ w1h, __half* __restrict__ w1l,
                             __half* __restrict__ w2h, __half* __restrict__ w2l)
{
    int i = blockIdx.x * blockDim.x + threadIdx.x;
    if (i < 256 * 256) {
        float v = W1[i];
        __half h = __float2half_rn(v);
        w1h[i] = h;
        w1l[i] = __float2half_rn(v - __half2float(h));
    }
    if (i < 256 * 128) {
        float v = W2[i];
        __half h = __float2half_rn(v);
        w2h[i] = h;
        w2l[i] = __float2half_rn(v - __half2float(h));
    }
}

// ========== FFMA2 score kernel (L3, proven) ==========
__device__ __forceinline__ unsigned long long lds64(const float* p) {
    unsigned long long v;
    unsigned a = (unsigned)__cvta_generic_to_shared(p);
    asm volatile("ld.shared.b64 %0, [%1];" : "=l"(v) : "r"(a));
    return v;
}
__device__ __forceinline__ void ffma2(unsigned long long& d, unsigned long long a,
                                      unsigned long long b) {
    asm volatile("fma.rn.f32x2 %0, %1, %2, %0;" : "+l"(d) : "l"(a), "l"(b));
}
__device__ __forceinline__ float2 up2(unsigned long long v) {
    float2 r;
    asm("mov.b64 {%0,%1}, %2;" : "=f"(r.x), "=f"(r.y) : "l"(v));
    return r;
}

template<int BN, int NT>
__global__ void __launch_bounds__(NT)
score_gemm(const float* __restrict__ A, const float* __restrict__ W,
           const float* __restrict__ bias, const float* __restrict__ w_atom,
           float* __restrict__ score_out, const int K, const int Ntot)
{
    constexpr int BM = 128, BK = 16, TM = 8, TN = 8;
    constexpr int TXN = BN / TN;
    constexpr int APITCH = BM + 4;
    constexpr int BPITCH = 2 * BN;
    constexpr int ASZ = BK * APITCH;
    constexpr int BSZ = BK * BPITCH;
    constexpr int A_IT = (BM * BK / 4) / NT;
    constexpr int B_IT = (BK * BN / 4) / NT;

    extern __shared__ float fsm[];
    float* Asm = fsm;
    float* Bsm = fsm + 2 * ASZ;
    float* sw  = Bsm + 2 * BSZ;

    const int tid = threadIdx.x;
    const int tx = tid % TXN;
    const int ty = tid / TXN;
    const int row0 = blockIdx.x * BM;

    if (tid < H3) sw[tid] = w_atom[tid];

    unsigned long long acc[4][8];
#pragma unroll
    for (int i = 0; i < 4; i++)
#pragma unroll
        for (int j = 0; j < 8; j++) acc[i][j] = 0ull;

    float4 ra[A_IT], rb[B_IT];
    auto fetchA = [&](int kt) {
#pragma unroll
        for (int i = 0; i < A_IT; i++) {
            int v = tid + i * NT, r = v >> 2, c4 = v & 3;
            ra[i] = *reinterpret_cast<const float4*>(&A[(size_t)(row0 + r) * K + kt + c4 * 4]);
        }
    };
    auto storeA = [&](int b) {
#pragma unroll
        for (int i = 0; i < A_IT; i++) {
            int v = tid + i * NT, r = v >> 2, c4 = v & 3;
            float* base = Asm + b * ASZ;
            base[(c4 * 4 + 0) * APITCH + r] = ra[i].x;
            base[(c4 * 4 + 1) * APITCH + r] = ra[i].y;
            base[(c4 * 4 + 2) * APITCH + r] = ra[i].z;
            base[(c4 * 4 + 3) * APITCH + r] = ra[i].w;
        }
    };
    auto fetchB = [&](int kt) {
#pragma unroll
        for (int i = 0; i < B_IT; i++) {
            int v = tid + i * NT, kr = v / (BN / 4), c4 = v % (BN / 4);
            rb[i] = *reinterpret_cast<const float4*>(&W[(size_t)(kt + kr) * Ntot + c4 * 4]);
        }
    };
    auto storeB = [&](int b) {
#pragma unroll
        for (int i = 0; i < B_IT; i++) {
            int v = tid + i * NT, kr = v / (BN / 4), c4 = v % (BN / 4);
            float* base = Bsm + b * BSZ + kr * BPITCH;
            float vv[4] = {rb[i].x, rb[i].y, rb[i].z, rb[i].w};
#pragma unroll
            for (int j = 0; j < 4; j++) {
                int col = c4 * 4 + j;
                int addr = (col % TN) * (2 * TXN) + 2 * (col / TN);
                *reinterpret_cast<float2*>(&base[addr]) = make_float2(vv[j], vv[j]);
            }
        }
    };

    fetchA(0); fetchB(0);
    storeA(0); storeB(0);
    __syncthreads();
    int buf = 0;
    for (int kt = 0; kt < K; kt += BK) {
        const bool nxt = (kt + BK < K);
        if (nxt) { fetchA(kt + BK); fetchB(kt + BK); }
        const float* Ab = Asm + buf * ASZ + ty * TM;
        const float* Bb = Bsm + buf * BSZ + 2 * tx;
#pragma unroll
        for (int k = 0; k < BK; k++) {
            unsigned long long ap[4], bp[8];
#pragma unroll
            for (int m = 0; m < 4; m++) ap[m] = lds64(Ab + k * APITCH + 2 * m);
#pragma unroll
            for (int n = 0; n < 8; n++) bp[n] = lds64(Bb + k * BPITCH + n * (2 * TXN));
#pragma unroll
            for (int m = 0; m < 4; m++)
#pragma unroll
                for (int n = 0; n < 8; n++) ffma2(acc[m][n], ap[m], bp[n]);
        }
        if (nxt) { storeA(buf ^ 1); storeB(buf ^ 1); }
        __syncthreads();
        buf ^= 1;
    }

    float wn = 0.f;
#pragma unroll
    for (int j = 0; j < H3; j++) wn += sw[j] * sw[j];
    const float nrm = sqrtf(wn);
    float bb[8], wa[8];
#pragma unroll
    for (int n = 0; n < 8; n++) { bb[n] = bias[tx * TN + n]; wa[n] = sw[tx * TN + n]; }
#pragma unroll
    for (int mp = 0; mp < 4; mp++) {
        float p0 = 0.f, p1 = 0.f;
#pragma unroll
        for (int n = 0; n < 8; n++) {
            float2 t = up2(acc[mp][n]);
            p0 += lrelu(t.x + bb[n]) * wa[n];
            p1 += lrelu(t.y + bb[n]) * wa[n];
        }
#pragma unroll
        for (int o = 1; o < TXN; o <<= 1) {
            p0 += __shfl_xor_sync(0xffffffffu, p0, o);
            p1 += __shfl_xor_sync(0xffffffffu, p1, o);
        }
        if (tx == 0) {
            int r = row0 + ty * TM + mp * 2;
            score_out[r]     = tanhf(p0 / nrm);
            score_out[r + 1] = tanhf(p1 / nrm);
        }
    }
}

// ========== topk + gather (proven) ==========
__global__ void topk_gather(const float* __restrict__ x, const float* __restrict__ pe,
                            const float* __restrict__ score,
                            const int* __restrict__ on_index,
                            float* __restrict__ out, const long long out_size)
{
    __shared__ float s[NPG];
    __shared__ int pos[NPG];
    __shared__ int sel[KSEL];
    const int g = blockIdx.x;
    const int tid = threadIdx.x;
    s[tid] = score[g * NPG + tid];
    __syncthreads();
    const float my = s[tid];
    int r = 0;
#pragma unroll 8
    for (int j = 0; j < NPG; j++) {
        float v = s[j];
        r += (v > my) || (v == my && j < tid);
    }
    pos[r] = tid;
    __syncthreads();
    if (tid == 0) {
        int c = 0;
        for (int rr = 0; rr < NPG && c < KSEL; rr++) {
            int node = pos[rr];
            if ((node & 1) == 0) sel[c++] = node;
        }
    }
    __syncthreads();

    const long long OFF_PERM = (long long)NGRAPH * KSEL * CIN;
    const long long OFF_SCON = OFF_PERM + (long long)NGRAPH * KSEL;
    const long long OFF_ONIX = OFF_SCON + (long long)NGRAPH * ONPG;
    const long long TOTAL    = OFF_ONIX + (long long)NGRAPH * ONPG;

    for (int idx = tid; idx < KSEL * CIN; idx += blockDim.x) {
        int c = idx >> 8;
        int ch = idx & (CIN - 1);
        int node = sel[c];
        size_t gn = (size_t)g * NPG + node;
        float xp = x[gn * CIN + ch] + pe[(size_t)node * CIN + ch];
        out[((size_t)g * KSEL + c) * CIN + ch] = xp * s[node];
    }
    if (out_size >= TOTAL) {
        if (tid < KSEL)
            out[OFF_PERM + g * KSEL + tid] = (float)(g * NPG + sel[tid]);
        if (tid < ONPG) {
            int oi = on_index[g * ONPG + tid];
            out[OFF_SCON + g * ONPG + tid] = s[oi - g * NPG];
            out[OFF_ONIX + g * ONPG + tid] = (float)oi;
        }
    }
}

// ========== launch ==========
extern "C" void kernel_launch(void* const* d_in, const int* in_sizes, int n_in,
                              void* d_out, int out_size)
{
    const float* x      = (const float*)d_in[0];
    const float* pe     = (const float*)d_in[1];
    const float* W1     = (const float*)d_in[2];
    const float* b1     = (const float*)d_in[3];
    const float* W2     = (const float*)d_in[4];
    const float* b2     = (const float*)d_in[5];
    const float* W3     = (const float*)d_in[6];
    const float* b3     = (const float*)d_in[7];
    const float* w_atom = (const float*)d_in[8];
    const int*   on_idx = (const int*)d_in[10];
    float* out = (float*)d_out;

    __half *h1h, *h1l, *w1h, *w1l, *w2h, *w2l;
    float *h2, *sc;
    cudaGetSymbolAddress((void**)&h1h, g_h1h);
    cudaGetSymbolAddress((void**)&h1l, g_h1l);
    cudaGetSymbolAddress((void**)&h2, g_h2);
    cudaGetSymbolAddress((void**)&sc, g_score);
    cudaGetSymbolAddress((void**)&w1h, g_w1h);
    cudaGetSymbolAddress((void**)&w1l, g_w1l);
    cudaGetSymbolAddress((void**)&w2h, g_w2h);
    cudaGetSymbolAddress((void**)&w2l, g_w2l);

    const int SMH = 2 * (2 * 128 * 40 + 2 * 32 * 136) * 2;        // 75776 B
    const int smemS = (2 * 16 * 132 + 2 * 16 * 128 + 64) * 4;     // score kernel

    static bool attr_done = false;
    if (!attr_done) {
        cudaFuncSetAttribute(hsplit_gemm<false, true>,
                             cudaFuncAttributeMaxDynamicSharedMemorySize, SMH);
        cudaFuncSetAttribute(hsplit_gemm<true, false>,
                             cudaFuncAttributeMaxDynamicSharedMemorySize, SMH);
        cudaFuncSetAttribute(score_gemm<64, 128>,
                             cudaFuncAttributeMaxDynamicSharedMemorySize, smemS);
        attr_done = true;
    }

    prep_weights<<<256, 256>>>(W1, W2, w1h, w1l, w2h, w2l);
    // L1: h1(fp16 split) = lrelu((x+pe) @ W1 + b1)
    hsplit_gemm<false, true><<<dim3(512, 2), 512, SMH>>>(
        x, pe, nullptr, nullptr, w1h, w1l, b1, nullptr, h1h, h1l, 256, 256);
    // L2: h2(fp32) = lrelu(h1 @ W2 + b2)
    hsplit_gemm<true, false><<<dim3(512, 1), 512, SMH>>>(
        nullptr, nullptr, h1h, h1l, w2h, w2l, b2, h2, nullptr, nullptr, 256, 128);
    // L3 + score
    score_gemm<64, 128><<<512, 128, smemS>>>(h2, W3, b3, w_atom, sc, 128, 64);
    // rank + select + gather
    topk_gather<<<NGRAPH, NPG>>>(x, pe, sc, on_idx, out, (long long)out_size);
}

// round 9
// speedup vs baseline: 2.8495x; 1.0893x over previous
#include <cuda_runtime.h>
#include <cuda_fp16.h>
#include <mma.h>
#include <math.h>
#include <stdint.h>

using namespace nvcuda;

#define NNODES 65536
#define NGRAPH 256
#define NPG    256
#define CIN    256
#define KSEL   16
#define ONPG   128
#define H3     64

// scratch (device globals; allocations forbidden)
__device__ __half g_h1h[(size_t)NNODES * 256];
__device__ __half g_h1l[(size_t)NNODES * 256];
__device__ __half g_h2h[(size_t)NNODES * 128];
__device__ __half g_h2l[(size_t)NNODES * 128];
__device__ float  g_score[NNODES];
__device__ __half g_w1h[256 * 256], g_w1l[256 * 256];   // W1 [K][N] fp16 split
__device__ __half g_w2h[256 * 128], g_w2l[256 * 128];   // W2 [K][N] fp16 split
__device__ __half g_w3h[128 * 64],  g_w3l[128 * 64];    // W3 [K][N] fp16 split

__device__ __forceinline__ float lrelu(float z) { return z > 0.0f ? z : 0.1f * z; }
__device__ __forceinline__ uint32_t smem_u32(const void* p) {
    uint32_t a;
    asm("{ .reg .u64 t; cvta.to.shared.u64 t, %1; cvt.u32.u64 %0, t; }" : "=r"(a) : "l"(p));
    return a;
}
__device__ __forceinline__ void cp16(uint32_t dst, const void* src) {
    asm volatile("cp.async.cg.shared.global [%0], [%1], 16;" :: "r"(dst), "l"(src));
}
#define CP_COMMIT() asm volatile("cp.async.commit_group;" ::: "memory")
#define CP_WAIT0()  asm volatile("cp.async.wait_group 0;" ::: "memory")

__device__ __forceinline__ uint32_t packh2(__half a, __half b) {
    return (uint32_t)__half_as_ushort(a) | ((uint32_t)__half_as_ushort(b) << 16);
}
__device__ __forceinline__ void sts16(uint32_t addr, uint32_t a, uint32_t b,
                                      uint32_t c, uint32_t d) {
    asm volatile("st.shared.v4.b32 [%0], {%1,%2,%3,%4};"
                 :: "r"(addr), "r"(a), "r"(b), "r"(c), "r"(d) : "memory");
}

// ========== fp16 3-split GEMM: out = lrelu(A @ W + bias) ==========
// A [M,K]: raw fp32 (+pe) split in-kernel, or pre-split fp16 hi/lo.
// W [K,N] pre-split fp16 hi/lo. CTA 128x128, KC=32, 512 thr = 16 warps (4x4).
template<bool PRESPLIT_A, bool SPLIT_OUT>
__global__ void __launch_bounds__(512)
hsplit_gemm(const float* __restrict__ Araw, const float* __restrict__ pe,
            const __half* __restrict__ AhG, const __half* __restrict__ AlG,
            const __half* __restrict__ BhG, const __half* __restrict__ BlG,
            const float* __restrict__ bias,
            float* __restrict__ outF, __half* __restrict__ outH, __half* __restrict__ outL,
            const int K, const int OutN)
{
    constexpr int KC = 32;
    constexpr int APITCH = 40;                 // halves per A row (32 + 8 pad)
    constexpr int BPITCH = 136;                // halves per B k-row (128 + 8 pad)
    constexpr int ASZ = 128 * APITCH;          // 5120 halves per split
    constexpr int BSZ = KC * BPITCH;           // 4352 halves per split
    constexpr int BUFH = 2 * ASZ + 2 * BSZ;    // 18944 halves per buffer

    extern __shared__ __half smh[];
    const uint32_t sb = smem_u32(smh);

    const int tid = threadIdx.x;
    const int wid = tid >> 5;
    const int wm = wid >> 2;                   // 0..3
    const int wn = wid & 3;                    // 0..3
    const int row0 = blockIdx.x * 128;
    const int col0 = blockIdx.y * 128;
    const int C = K / KC;

    auto issue = [&](int kt, int b) {
        const uint32_t d0 = sb + (uint32_t)b * (BUFH * 2u);
        {   // B: 512 threads = 32 rows * 16 chunks
            int kr = tid >> 4, cc = tid & 15;
            const uint32_t so = (uint32_t)(kr * BPITCH + cc * 8) * 2u;
            const size_t g = (size_t)(kt + kr) * OutN + col0 + cc * 8;
            cp16(d0 + 2u * ASZ * 2u + so, BhG + g);
            cp16(d0 + (2u * ASZ + BSZ) * 2u + so, BlG + g);
        }
        if (PRESPLIT_A) {   // A: 128 rows * 4 chunks
            int r = tid >> 2, cc = tid & 3;
            const uint32_t so = (uint32_t)(r * APITCH + cc * 8) * 2u;
            const size_t g = (size_t)(row0 + r) * K + kt + cc * 8;
            cp16(d0 + so, AhG + g);
            cp16(d0 + ASZ * 2u + so, AlG + g);
        }
    };

    float4 fa[2], fp[2];
    auto fetchA = [&](int kt) {
        int r = tid >> 2, q = tid & 3;
#pragma unroll
        for (int i = 0; i < 2; i++) {
            fa[i] = *reinterpret_cast<const float4*>(&Araw[(size_t)(row0 + r) * K + kt + q * 8 + i * 4]);
            fp[i] = *reinterpret_cast<const float4*>(&pe[(size_t)((row0 + r) & (NPG - 1)) * CIN + kt + q * 8 + i * 4]);
        }
    };
    auto storeA = [&](int b) {
        int r = tid >> 2, q = tid & 3;
        float v[8] = {fa[0].x + fp[0].x, fa[0].y + fp[0].y, fa[0].z + fp[0].z, fa[0].w + fp[0].w,
                      fa[1].x + fp[1].x, fa[1].y + fp[1].y, fa[1].z + fp[1].z, fa[1].w + fp[1].w};
        __half hh[8], ll[8];
#pragma unroll
        for (int j = 0; j < 8; j++) {
            hh[j] = __float2half_rn(v[j]);
            ll[j] = __float2half_rn(v[j] - __half2float(hh[j]));
        }
        const uint32_t d0 = sb + (uint32_t)b * (BUFH * 2u);
        const uint32_t so = (uint32_t)(r * APITCH + q * 8) * 2u;
        sts16(d0 + so, packh2(hh[0], hh[1]), packh2(hh[2], hh[3]),
                       packh2(hh[4], hh[5]), packh2(hh[6], hh[7]));
        sts16(d0 + ASZ * 2u + so, packh2(ll[0], ll[1]), packh2(ll[2], ll[3]),
                                  packh2(ll[4], ll[5]), packh2(ll[6], ll[7]));
    };

    wmma::fragment<wmma::accumulator, 16, 16, 16, float> acc[2][2];
#pragma unroll
    for (int i = 0; i < 2; i++)
#pragma unroll
        for (int j = 0; j < 2; j++) wmma::fill_fragment(acc[i][j], 0.0f);

    if (!PRESPLIT_A) fetchA(0);
    issue(0, 0); CP_COMMIT();
    if (!PRESPLIT_A) storeA(0);
    CP_WAIT0();
    __syncthreads();

    for (int c = 0; c < C; c++) {
        const bool nxt = (c + 1 < C);
        if (nxt) {
            if (!PRESPLIT_A) fetchA((c + 1) * KC);
            issue((c + 1) * KC, (c + 1) & 1);
            CP_COMMIT();
        }
        const __half* Ah = smh + (c & 1) * BUFH;
        const __half* Al = Ah + ASZ;
        const __half* Bh = Al + ASZ;
        const __half* Bl = Bh + BSZ;
#pragma unroll
        for (int ks = 0; ks < 2; ks++) {
            const int k0 = ks * 16;
            wmma::fragment<wmma::matrix_b, 16, 16, 16, __half, wmma::row_major> fbh[2], fbl[2];
#pragma unroll
            for (int j = 0; j < 2; j++) {
                wmma::load_matrix_sync(fbh[j], Bh + k0 * BPITCH + wn * 32 + j * 16, BPITCH);
                wmma::load_matrix_sync(fbl[j], Bl + k0 * BPITCH + wn * 32 + j * 16, BPITCH);
            }
#pragma unroll
            for (int i = 0; i < 2; i++) {
                wmma::fragment<wmma::matrix_a, 16, 16, 16, __half, wmma::row_major> fah, fal;
                wmma::load_matrix_sync(fah, Ah + (wm * 32 + i * 16) * APITCH + k0, APITCH);
                wmma::load_matrix_sync(fal, Al + (wm * 32 + i * 16) * APITCH + k0, APITCH);
#pragma unroll
                for (int j = 0; j < 2; j++) {
                    wmma::mma_sync(acc[i][j], fah, fbh[j], acc[i][j]);
                    wmma::mma_sync(acc[i][j], fal, fbh[j], acc[i][j]);
                    wmma::mma_sync(acc[i][j], fah, fbl[j], acc[i][j]);
                }
            }
        }
        if (nxt && !PRESPLIT_A) storeA((c + 1) & 1);
        CP_WAIT0();
        __syncthreads();
    }

    constexpr int CP = 132;
    float* Cs = reinterpret_cast<float*>(smh);
#pragma unroll
    for (int i = 0; i < 2; i++)
#pragma unroll
        for (int j = 0; j < 2; j++)
            wmma::store_matrix_sync(&Cs[(wm * 32 + i * 16) * CP + wn * 32 + j * 16],
                                    acc[i][j], CP, wmma::mem_row_major);
    __syncthreads();

#pragma unroll
    for (int it = 0; it < 8; it++) {
        int v = tid + it * 512;
        int r = v >> 5, cc = (v & 31) * 4;
        float4 s = *reinterpret_cast<float4*>(&Cs[r * CP + cc]);
        const float* bp = bias + col0 + cc;
        s.x = lrelu(s.x + bp[0]);
        s.y = lrelu(s.y + bp[1]);
        s.z = lrelu(s.z + bp[2]);
        s.w = lrelu(s.w + bp[3]);
        const size_t o = (size_t)(row0 + r) * OutN + col0 + cc;
        if (SPLIT_OUT) {
            __half h0 = __float2half_rn(s.x), h1 = __float2half_rn(s.y);
            __half h2v = __float2half_rn(s.z), h3 = __float2half_rn(s.w);
            *reinterpret_cast<__half2*>(outH + o)     = __halves2half2(h0, h1);
            *reinterpret_cast<__half2*>(outH + o + 2) = __halves2half2(h2v, h3);
            *reinterpret_cast<__half2*>(outL + o) = __halves2half2(
                __float2half_rn(s.x - __half2float(h0)), __float2half_rn(s.y - __half2float(h1)));
            *reinterpret_cast<__half2*>(outL + o + 2) = __halves2half2(
                __float2half_rn(s.z - __half2float(h2v)), __float2half_rn(s.w - __half2float(h3)));
        } else {
            *reinterpret_cast<float4*>(&outF[o]) = s;
        }
    }
}

// ========== prep: fp16-split W1, W2, W3 (natural [K][N] layout) ==========
__global__ void prep_weights(const float* __restrict__ W1, const float* __restrict__ W2,
                             const float* __restrict__ W3,
                             __half* __restrict__ w1h, __half* __restrict__ w1l,
                             __half* __restrict__ w2h, __half* __restrict__ w2l,
                             __half* __restrict__ w3h, __half* __restrict__ w3l)
{
    int i = blockIdx.x * blockDim.x + threadIdx.x;
    if (i < 256 * 256) {
        float v = W1[i];
        __half h = __float2half_rn(v);
        w1h[i] = h;
        w1l[i] = __float2half_rn(v - __half2float(h));
    }
    if (i < 256 * 128) {
        float v = W2[i];
        __half h = __float2half_rn(v);
        w2h[i] = h;
        w2l[i] = __float2half_rn(v - __half2float(h));
    }
    if (i < 128 * 64) {
        float v = W3[i];
        __half h = __float2half_rn(v);
        w3h[i] = h;
        w3l[i] = __float2half_rn(v - __half2float(h));
    }
}

// ========== fp16 3-split L3+score: score = tanh(lrelu(h2@W3+b3).w/||w||) ==========
// h2 pre-split [M,128]; W3 pre-split [128,64]. CTA: 128 rows, 256 thr = 8 warps
// (4m x 2n), warp tile 32x32. Whole K=128 staged once.
__global__ void __launch_bounds__(256)
score_hmma(const __half* __restrict__ AhG, const __half* __restrict__ AlG,
           const __half* __restrict__ BhG, const __half* __restrict__ BlG,
           const float* __restrict__ bias, const float* __restrict__ w_atom,
           float* __restrict__ score_out)
{
    constexpr int K = 128, N = 64;
    constexpr int APITCH = 136;                // halves (128 + 8)
    constexpr int BPITCH = 72;                 // halves (64 + 8)
    constexpr int ASZ = 128 * APITCH;          // 17408 halves per split
    constexpr int BSZ = K * BPITCH;            // 9216 halves per split
    constexpr int TAIL = 2 * ASZ + 2 * BSZ;    // 53248 halves = 106496 B

    extern __shared__ __half smh[];
    const uint32_t sb = smem_u32(smh);
    float* sw = reinterpret_cast<float*>(smh + TAIL);        // [64] w_atom
    float* sbias = sw + 64;                                  // [64] b3

    const int tid = threadIdx.x;
    const int wid = tid >> 5;
    const int wm = wid >> 1;                   // 0..3
    const int wn = wid & 1;                    // 0..1
    const int row0 = blockIdx.x * 128;

    if (tid < 64) { sw[tid] = w_atom[tid]; sbias[tid] = bias[tid]; }

    // A: 128 rows x 16 chunks (8 halves each) = 2048 chunks -> 8/thread per split
#pragma unroll
    for (int t = 0; t < 8; t++) {
        int v = tid + t * 256;
        int r = v >> 4, cc = (v & 15) * 8;
        const uint32_t so = (uint32_t)(r * APITCH + cc) * 2u;
        const size_t g = (size_t)(row0 + r) * K + cc;
        cp16(sb + so, AhG + g);
        cp16(sb + ASZ * 2u + so, AlG + g);
    }
    // B: 128 rows x 8 chunks = 1024 chunks -> 4/thread per split
#pragma unroll
    for (int t = 0; t < 4; t++) {
        int v = tid + t * 256;
        int kr = v >> 3, bc = (v & 7) * 8;
        const uint32_t so = (uint32_t)(kr * BPITCH + bc) * 2u;
        const size_t g = (size_t)kr * N + bc;
        cp16(sb + 2u * ASZ * 2u + so, BhG + g);
        cp16(sb + (2u * ASZ + BSZ) * 2u + so, BlG + g);
    }
    CP_COMMIT();
    CP_WAIT0();
    __syncthreads();

    const __half* Ah = smh;
    const __half* Al = Ah + ASZ;
    const __half* Bh = Al + ASZ;
    const __half* Bl = Bh + BSZ;

    wmma::fragment<wmma::accumulator, 16, 16, 16, float> acc[2][2];
#pragma unroll
    for (int i = 0; i < 2; i++)
#pragma unroll
        for (int j = 0; j < 2; j++) wmma::fill_fragment(acc[i][j], 0.0f);

#pragma unroll
    for (int ks = 0; ks < 8; ks++) {
        const int k0 = ks * 16;
        wmma::fragment<wmma::matrix_b, 16, 16, 16, __half, wmma::row_major> fbh[2], fbl[2];
#pragma unroll
        for (int j = 0; j < 2; j++) {
            wmma::load_matrix_sync(fbh[j], Bh + k0 * BPITCH + wn * 32 + j * 16, BPITCH);
            wmma::load_matrix_sync(fbl[j], Bl + k0 * BPITCH + wn * 32 + j * 16, BPITCH);
        }
#pragma unroll
        for (int i = 0; i < 2; i++) {
            wmma::fragment<wmma::matrix_a, 16, 16, 16, __half, wmma::row_major> fah, fal;
            wmma::load_matrix_sync(fah, Ah + (wm * 32 + i * 16) * APITCH + k0, APITCH);
            wmma::load_matrix_sync(fal, Al + (wm * 32 + i * 16) * APITCH + k0, APITCH);
#pragma unroll
            for (int j = 0; j < 2; j++) {
                wmma::mma_sync(acc[i][j], fah, fbh[j], acc[i][j]);
                wmma::mma_sync(acc[i][j], fal, fbh[j], acc[i][j]);
                wmma::mma_sync(acc[i][j], fah, fbl[j], acc[i][j]);
            }
        }
    }
    __syncthreads();

    // stage C (128 x 64, pitch 68) in smem
    constexpr int CPI = 68;
    float* Cs = reinterpret_cast<float*>(smh);
#pragma unroll
    for (int i = 0; i < 2; i++)
#pragma unroll
        for (int j = 0; j < 2; j++)
            wmma::store_matrix_sync(&Cs[(wm * 32 + i * 16) * CPI + wn * 32 + j * 16],
                                    acc[i][j], CPI, wmma::mem_row_major);
    __syncthreads();

    if (tid < 128) {
        float wn2 = 0.f;
#pragma unroll
        for (int j = 0; j < H3; j++) wn2 += sw[j] * sw[j];
        const float nrm = sqrtf(wn2);
        float p = 0.f;
        const float* cr = Cs + tid * CPI;
#pragma unroll
        for (int c = 0; c < H3; c++) p += lrelu(cr[c] + sbias[c]) * sw[c];
        score_out[row0 + tid] = tanhf(p / nrm);
    }
}

// ========== topk + gather (hardened: node clamped; UB impossible) ==========
__global__ void topk_gather(const float* __restrict__ x, const float* __restrict__ pe,
                            const float* __restrict__ score,
                            const int* __restrict__ on_index,
                            float* __restrict__ out, const long long out_size)
{
    __shared__ float s[NPG];
    __shared__ int pos[NPG];
    __shared__ int sel[KSEL];
    const int g = blockIdx.x;
    const int tid = threadIdx.x;
    s[tid] = score[g * NPG + tid];
    pos[tid] = 0;                 // defensive init: rank collisions can't leave garbage
    __syncthreads();
    const float my = s[tid];
    int r = 0;
#pragma unroll 8
    for (int j = 0; j < NPG; j++) {
        float v = s[j];
        r += (v > my) || (v == my && j < tid);
    }
    pos[r] = tid;
    __syncthreads();
    if (tid == 0) {
        int c = 0;
        for (int rr = 0; rr < NPG && c < KSEL; rr++) {
            int node = pos[rr];
            if ((node & 1) == 0) sel[c++] = node;
        }
        // pathological fallback (ties/NaN): pad with valid even nodes
        int fill = 0;
        while (c < KSEL) { sel[c++] = fill; fill += 2; }
    }
    __syncthreads();

    const long long OFF_PERM = (long long)NGRAPH * KSEL * CIN;
    const long long OFF_SCON = OFF_PERM + (long long)NGRAPH * KSEL;
    const long long OFF_ONIX = OFF_SCON + (long long)NGRAPH * ONPG;
    const long long TOTAL    = OFF_ONIX + (long long)NGRAPH * ONPG;

    for (int idx = tid; idx < KSEL * CIN; idx += blockDim.x) {
        int c = idx >> 8;
        int ch = idx & (CIN - 1);
        int node = sel[c] & (NPG - 1);
        size_t gn = (size_t)g * NPG + node;
        float xp = x[gn * CIN + ch] + pe[(size_t)node * CIN + ch];
        out[((size_t)g * KSEL + c) * CIN + ch] = xp * s[node];
    }
    if (out_size >= TOTAL) {
        if (tid < KSEL)
            out[OFF_PERM + g * KSEL + tid] = (float)(g * NPG + (sel[tid] & (NPG - 1)));
        if (tid < ONPG) {
            int oi = on_index[g * ONPG + tid];
            out[OFF_SCON + g * ONPG + tid] = s[(oi - g * NPG) & (NPG - 1)];
            out[OFF_ONIX + g * ONPG + tid] = (float)oi;
        }
    }
}

// ========== launch ==========
extern "C" void kernel_launch(void* const* d_in, const int* in_sizes, int n_in,
                              void* d_out, int out_size)
{
    const float* x      = (const float*)d_in[0];
    const float* pe     = (const float*)d_in[1];
    const float* W1     = (const float*)d_in[2];
    const float* b1     = (const float*)d_in[3];
    const float* W2     = (const float*)d_in[4];
    const float* b2     = (const float*)d_in[5];
    const float* W3     = (const float*)d_in[6];
    const float* b3     = (const float*)d_in[7];
    const float* w_atom = (const float*)d_in[8];
    const int*   on_idx = (const int*)d_in[10];
    float* out = (float*)d_out;

    __half *h1h, *h1l, *h2h, *h2l, *w1h, *w1l, *w2h, *w2l, *w3h, *w3l;
    float *sc;
    cudaGetSymbolAddress((void**)&h1h, g_h1h);
    cudaGetSymbolAddress((void**)&h1l, g_h1l);
    cudaGetSymbolAddress((void**)&h2h, g_h2h);
    cudaGetSymbolAddress((void**)&h2l, g_h2l);
    cudaGetSymbolAddress((void**)&sc, g_score);
    cudaGetSymbolAddress((void**)&w1h, g_w1h);
    cudaGetSymbolAddress((void**)&w1l, g_w1l);
    cudaGetSymbolAddress((void**)&w2h, g_w2h);
    cudaGetSymbolAddress((void**)&w2l, g_w2l);
    cudaGetSymbolAddress((void**)&w3h, g_w3h);
    cudaGetSymbolAddress((void**)&w3l, g_w3l);

    const int SMH = 2 * (2 * 128 * 40 + 2 * 32 * 136) * 2;        // 75776 B
    const int SMS = (2 * 128 * 136 + 2 * 128 * 72) * 2 + 512;     // 107008 B

    static bool attr_done = false;
    if (!attr_done) {
        cudaFuncSetAttribute(hsplit_gemm<false, true>,
                             cudaFuncAttributeMaxDynamicSharedMemorySize, SMH);
        cudaFuncSetAttribute(hsplit_gemm<true, true>,
                             cudaFuncAttributeMaxDynamicSharedMemorySize, SMH);
        cudaFuncSetAttribute(score_hmma,
                             cudaFuncAttributeMaxDynamicSharedMemorySize, SMS);
        attr_done = true;
    }

    prep_weights<<<256, 256>>>(W1, W2, W3, w1h, w1l, w2h, w2l, w3h, w3l);
    // L1: h1(fp16 split) = lrelu((x+pe) @ W1 + b1)
    hsplit_gemm<false, true><<<dim3(512, 2), 512, SMH>>>(
        x, pe, nullptr, nullptr, w1h, w1l, b1, nullptr, h1h, h1l, 256, 256);
    // L2: h2(fp16 split) = lrelu(h1 @ W2 + b2)
    hsplit_gemm<true, true><<<dim3(512, 1), 512, SMH>>>(
        nullptr, nullptr, h1h, h1l, w2h, w2l, b2, nullptr, h2h, h2l, 256, 128);
    // L3 + score (fp16 3-split tensor path)
    score_hmma<<<512, 256, SMS>>>(h2h, h2l, w3h, w3l, b3, w_atom, sc);
    // rank + select + gather
    topk_gather<<<NGRAPH, NPG>>>(x, pe, sc, on_idx, out, (long long)out_size);
}